// round 15
// baseline (speedup 1.0000x reference)
#include <cuda_runtime.h>
#include <cuda_bf16.h>
#include <math.h>
#include <stdint.h>

#define BB   16
#define NN   64
#define PREV 6
#define PRED 30
#define HH   256
#define EE   (NN*(NN-1))      // 4032
#define ROWS_E (BB*EE)        // 64512
#define ROWS_N (BB*NN)        // 1024

// ---------------- static scratch ----------------
__device__ float d_x[ROWS_N*HH];
__device__ float d_xTop[ROWS_N*HH];
__device__ float d_xBot[ROWS_N*HH];
__device__ __nv_bfloat16 d_h2[ROWS_E*HH];     // h2 bf16
__device__ float d_inc[ROWS_N*HH];
__device__ float d_incsq[ROWS_N*HH];
__device__ float d_outg[ROWS_N*HH];
__device__ float d_nh1[ROWS_N*HH];
__device__ float d_mraw[ROWS_N*HH];
__device__ float d_fused[ROWS_N*HH];
__device__ float d_ae[HH], d_ce[HH], d_an[HH], d_cn[HH];
__device__ int   d_recv[EE], d_send[EE];
__device__ int   d_listrec[NN*EE], d_listsend[NN*EE];
__device__ int   d_cntrec[NN], d_cntsend[NN];
__device__ float d_invdegrec[NN], d_invdegsend[NN];
__device__ __nv_bfloat16 d_w2t[HH*HH];   // W2^T in bf16: [n][k]

__device__ __forceinline__ float elu_f(float x)  { return x > 0.f ? x : (expf(x) - 1.f); }
__device__ __forceinline__ float elu_ff(float x) { return x > 0.f ? x : (__expf(x) - 1.f); }

__device__ __forceinline__ unsigned f2tf32(float x) {
    unsigned r;
    asm("cvt.rna.tf32.f32 %0, %1;" : "=r"(r) : "f"(x));
    return r;
}
__device__ __forceinline__ unsigned packbf2(float lo, float hi) {
    __nv_bfloat162 v = __floats2bfloat162_rn(lo, hi);
    return *reinterpret_cast<unsigned*>(&v);
}
__device__ __forceinline__ uint32_t smem_u32(const void* p) {
    uint32_t a;
    asm("{ .reg .u64 t; cvta.to.shared.u64 t, %1; cvt.u32.u64 %0, t; }" : "=r"(a) : "l"(p));
    return a;
}

#define LDSM4(r0,r1,r2,r3,addr) \
    asm volatile("ldmatrix.sync.aligned.m8n8.x4.shared.b16 {%0,%1,%2,%3}, [%4];" \
        : "=r"(r0), "=r"(r1), "=r"(r2), "=r"(r3) : "r"(addr))

#define CP_ASYNC16(dst, src) \
    asm volatile("cp.async.ca.shared.global [%0], [%1], 16;" :: "r"(dst), "l"(src) : "memory")
#define CP_COMMIT() asm volatile("cp.async.commit_group;" ::: "memory")
#define CP_WAIT(n)  asm volatile("cp.async.wait_group %0;" :: "n"(n) : "memory")

// ---------------- fused prep: derive + traj + W2^T + per-node lists ----------------
__global__ void prep_kernel(const float* __restrict__ rel_rec,
                            const float* __restrict__ rel_send,
                            int* __restrict__ recv_idx, int* __restrict__ send_idx,
                            const float* __restrict__ centers,
                            const float* __restrict__ W, const float* __restrict__ bias,
                            const float* __restrict__ W2, __nv_bfloat16* __restrict__ w2t,
                            float* __restrict__ x,
                            int* __restrict__ list_rec, int* __restrict__ list_send,
                            int* __restrict__ cnt_rec, int* __restrict__ cnt_send,
                            float* __restrict__ invdeg_rec, float* __restrict__ invdeg_send) {
    if (blockIdx.x < 16) {
        int e = blockIdx.x * 256 + threadIdx.x;
        if (e >= EE) return;
        int r = 0, s = 0; float br = -1.f, bs = -1.f;
        for (int n = 0; n < NN; n++) {
            float vr = rel_rec[e*NN + n];
            float vs = rel_send[e*NN + n];
            if (vr > br) { br = vr; r = n; }
            if (vs > bs) { bs = vs; s = n; }
        }
        recv_idx[e] = r; send_idx[e] = s;
        return;
    }
    if (blockIdx.x >= 1296) {
        int id = blockIdx.x - 1296;
        if (threadIdx.x >= 64) return;
        const bool isSend = id >= NN;
        const int n = id & (NN-1);
        const float* __restrict__ oneHot = (isSend ? rel_send : rel_rec);
        int* __restrict__ list = (isSend ? list_send : list_rec) + n*EE;
        const int t = threadIdx.x;
        const int CH = EE / 64;
        const int base = t * CH;
        int c = 0;
        for (int i = 0; i < CH; i++) c += (oneHot[(base+i)*NN + n] > 0.5f) ? 1 : 0;
        __shared__ int pre[64];
        pre[t] = c;
        __syncthreads();
        for (int off = 1; off < 64; off <<= 1) {
            int v = (t >= off) ? pre[t-off] : 0;
            __syncthreads();
            pre[t] += v;
            __syncthreads();
        }
        int offset = pre[t] - c;
        for (int i = 0; i < CH; i++) {
            int e = base + i;
            if (oneHot[e*NN + n] > 0.5f) list[offset++] = e;
        }
        if (t == 63) {
            int tot = pre[63];
            float iv = tot ? 1.f/(float)tot : 1.f;
            if (isSend) { cnt_send[n] = tot; invdeg_send[n] = iv; }
            else        { cnt_rec[n]  = tot; invdeg_rec[n]  = iv; }
        }
        return;
    }
    if (blockIdx.x >= 16 + ROWS_N) {
        int n = blockIdx.x - 16 - ROWS_N;
        int k = threadIdx.x;
        w2t[n*HH + k] = __float2bfloat16(W2[k*HH + n]);
        return;
    }
    int row = blockIdx.x - 16;
    int h = threadIdx.x;
    __shared__ float rp[PREV*2];
    if (h < PREV*2) {
        int p = h >> 1, c = h & 1;
        float v = 0.f;
        if (p > 0) v = centers[row*PREV*2 + p*2 + c] - centers[row*PREV*2 + (p-1)*2 + c];
        rp[h] = v;
    }
    __syncthreads();
    float acc = bias[h];
    #pragma unroll
    for (int k = 0; k < PREV*2; k++) acc += rp[k] * W[k*HH + h];
    x[row*HH + h] = acc;
}

// =======================================================================
// Small-GEMM v3: K-step 64 (unchanged from R14 passing version)
// =======================================================================
#define GEMM_SMEM ((2*64*68 + 2*64*72)*4)

template<int AMODE, bool ELU>
__global__ __launch_bounds__(256)
void mma_gemm_v3(const float* __restrict__ A0, const float* __restrict__ A1,
                 const float* __restrict__ aVec, const float* __restrict__ cVec,
                 const float* __restrict__ invDegR, const float* __restrict__ invDegS,
                 const float* __restrict__ B0, const float* __restrict__ B1,
                 const float* __restrict__ bias,
                 float* __restrict__ C0, float* __restrict__ C1,
                 int M, int N, int K) {
    const float* __restrict__ Bm = (blockIdx.z == 0) ? B0 : B1;
    float* __restrict__ C = (blockIdx.z == 0) ? C0 : C1;

    extern __shared__ float gsm[];
    float* Asm = gsm;                       // [2][64][68]
    float* Bsm = gsm + 2*64*68;             // [2][64][72]

    const int tid  = threadIdx.x;
    const int lane = tid & 31;
    const int warp = tid >> 5;
    const int warpM = warp & 1;
    const int warpN = warp >> 1;
    const int g  = lane >> 2;
    const int t4 = lane & 3;
    const int row0 = blockIdx.y * 64;
    const int col0 = blockIdx.x * 64;

    int arow[4], akq[4], bkk[4], bq[4];
    #pragma unroll
    for (int it = 0; it < 4; it++) {
        int ta = it*256 + tid;
        akq[it] = ta & 15;  arow[it] = ta >> 4;
        bq[it]  = ta & 15;  bkk[it]  = ta >> 4;
    }

    float4 pa[4], pb[4];

    auto prefetch = [&](int k0) {
        #pragma unroll
        for (int it = 0; it < 4; it++) {
            int gk = k0 + akq[it]*4;
            if (AMODE == 0) {
                pa[it] = *reinterpret_cast<const float4*>(&A0[(long)(row0+arow[it])*K + gk]);
            } else {
                const float* src = (gk >= HH) ? A1 : A0;
                pa[it] = *reinterpret_cast<const float4*>(&src[(long)(row0+arow[it])*HH + (gk & (HH-1))]);
            }
            int c0 = col0 + bq[it]*4;
            pb[it] = *reinterpret_cast<const float4*>(&Bm[(long)(k0+bkk[it])*N + c0]);
        }
    };

    auto store = [&](int s, int k0) {
        #pragma unroll
        for (int it = 0; it < 4; it++) {
            int gk = k0 + akq[it]*4;
            float4 v = pa[it];
            if (AMODE == 1) {
                int col = gk & (HH-1);
                float invd = ((gk >= HH) ? invDegS : invDegR)[(row0+arow[it]) & (NN-1)];
                float4 a4 = *reinterpret_cast<const float4*>(&aVec[col]);
                float4 c4 = *reinterpret_cast<const float4*>(&cVec[col]);
                v.x = a4.x*(v.x*invd)+c4.x; v.y = a4.y*(v.y*invd)+c4.y;
                v.z = a4.z*(v.z*invd)+c4.z; v.w = a4.w*(v.w*invd)+c4.w;
            } else if (AMODE == 2) {
                if (gk >= HH) {
                    int col = gk & (HH-1);
                    float4 a4 = *reinterpret_cast<const float4*>(&aVec[col]);
                    float4 c4 = *reinterpret_cast<const float4*>(&cVec[col]);
                    v.x = a4.x*v.x+c4.x; v.y = a4.y*v.y+c4.y;
                    v.z = a4.z*v.z+c4.z; v.w = a4.w*v.w+c4.w;
                }
            }
            float* ap = &Asm[(s*64 + arow[it])*68 + akq[it]*4];
            reinterpret_cast<unsigned*>(ap)[0] = f2tf32(v.x);
            reinterpret_cast<unsigned*>(ap)[1] = f2tf32(v.y);
            reinterpret_cast<unsigned*>(ap)[2] = f2tf32(v.z);
            reinterpret_cast<unsigned*>(ap)[3] = f2tf32(v.w);

            float4 w = pb[it];
            float* bp = &Bsm[(s*64 + bkk[it])*72 + bq[it]*4];
            reinterpret_cast<unsigned*>(bp)[0] = f2tf32(w.x);
            reinterpret_cast<unsigned*>(bp)[1] = f2tf32(w.y);
            reinterpret_cast<unsigned*>(bp)[2] = f2tf32(w.z);
            reinterpret_cast<unsigned*>(bp)[3] = f2tf32(w.w);
        }
    };

    float acc[2][2][4] = {};
    const int nIter = K >> 6;

    prefetch(0);
    store(0, 0);
    __syncthreads();

    for (int i = 0; i < nIter; i++) {
        int cur = i & 1;
        if (i + 1 < nIter) prefetch((i+1) * 64);

        const unsigned* Ac = reinterpret_cast<const unsigned*>(&Asm[(cur*64)*68]);
        const unsigned* Bc = reinterpret_cast<const unsigned*>(&Bsm[(cur*64)*72]);

        #pragma unroll
        for (int ks = 0; ks < 64; ks += 8) {
            unsigned afr[2][4];
            #pragma unroll
            for (int ii = 0; ii < 2; ii++) {
                int r = warpM*32 + ii*16;
                afr[ii][0] = Ac[(r + g    )*68 + ks + t4    ];
                afr[ii][1] = Ac[(r + g + 8)*68 + ks + t4    ];
                afr[ii][2] = Ac[(r + g    )*68 + ks + t4 + 4];
                afr[ii][3] = Ac[(r + g + 8)*68 + ks + t4 + 4];
            }
            unsigned bfr[2][2];
            #pragma unroll
            for (int j = 0; j < 2; j++) {
                int nn = warpN*16 + j*8 + g;
                bfr[j][0] = Bc[(ks + t4    )*72 + nn];
                bfr[j][1] = Bc[(ks + t4 + 4)*72 + nn];
            }
            #pragma unroll
            for (int ii = 0; ii < 2; ii++)
                #pragma unroll
                for (int j = 0; j < 2; j++)
                    asm volatile(
                        "mma.sync.aligned.m16n8k8.row.col.f32.tf32.tf32.f32 "
                        "{%0,%1,%2,%3}, {%4,%5,%6,%7}, {%8,%9}, {%0,%1,%2,%3};"
                        : "+f"(acc[ii][j][0]), "+f"(acc[ii][j][1]),
                          "+f"(acc[ii][j][2]), "+f"(acc[ii][j][3])
                        : "r"(afr[ii][0]), "r"(afr[ii][1]), "r"(afr[ii][2]), "r"(afr[ii][3]),
                          "r"(bfr[j][0]), "r"(bfr[j][1]));
        }
        if (i + 1 < nIter) store(cur ^ 1, (i+1) * 64);
        __syncthreads();
    }

    #pragma unroll
    for (int i = 0; i < 2; i++) {
        int r = row0 + warpM*32 + i*16 + g;
        #pragma unroll
        for (int j = 0; j < 2; j++) {
            int c = col0 + warpN*16 + j*8 + t4*2;
            #pragma unroll
            for (int h = 0; h < 2; h++) {
                int cc = c + h;
                float bb = bias ? bias[cc] : 0.f;
                float v0 = acc[i][j][h]   + bb;
                float v1 = acc[i][j][2+h] + bb;
                if (ELU) { v0 = elu_f(v0); v1 = elu_f(v1); }
                C[(long)r*N + cc]     = v0;
                C[(long)(r+8)*N + cc] = v1;
            }
        }
    }
}

// =======================================================================
// Pred GEMM + cumsum epilogue (unchanged)
// =======================================================================
__global__ __launch_bounds__(256)
void pred_pos_kernel(const float* __restrict__ A0, const float* __restrict__ Bm,
                     const float* __restrict__ bias, const float* __restrict__ centers,
                     float* __restrict__ out) {
    const int N = PRED*2;
    const int K = HH;
    __shared__ unsigned Asm[64][36];
    __shared__ unsigned Bsm[32][72];
    __shared__ float Cs[64][64];
    const int tid  = threadIdx.x;
    const int lane = tid & 31;
    const int warp = tid >> 5;
    const int warpM = warp & 1;
    const int warpN = warp >> 1;
    const int g  = lane >> 2;
    const int t4 = lane & 3;
    const int row0 = blockIdx.y * 64;

    int arow[2], akq[2], bkk[2], bq[2];
    #pragma unroll
    for (int it = 0; it < 2; it++) {
        int ta = it*256 + tid;
        akq[it] = ta & 7;  arow[it] = ta >> 3;
        bkk[it] = ta >> 4; bq[it]  = ta & 15;
    }
    float4 pa[2], pb[2];
    #pragma unroll
    for (int it = 0; it < 2; it++) {
        pa[it] = *reinterpret_cast<const float4*>(&A0[(long)(row0+arow[it])*K + akq[it]*4]);
        int c0 = bq[it]*4;
        float4 v;
        v.x = (c0+0 < N) ? Bm[(long)bkk[it]*N + c0+0] : 0.f;
        v.y = (c0+1 < N) ? Bm[(long)bkk[it]*N + c0+1] : 0.f;
        v.z = (c0+2 < N) ? Bm[(long)bkk[it]*N + c0+2] : 0.f;
        v.w = (c0+3 < N) ? Bm[(long)bkk[it]*N + c0+3] : 0.f;
        pb[it] = v;
    }

    float acc[2][2][4] = {};
    for (int k0 = 0; k0 < K; k0 += 32) {
        #pragma unroll
        for (int it = 0; it < 2; it++) {
            float4 v = pa[it];
            Asm[arow[it]][akq[it]*4+0] = f2tf32(v.x);
            Asm[arow[it]][akq[it]*4+1] = f2tf32(v.y);
            Asm[arow[it]][akq[it]*4+2] = f2tf32(v.z);
            Asm[arow[it]][akq[it]*4+3] = f2tf32(v.w);
            float4 w = pb[it];
            Bsm[bkk[it]][bq[it]*4+0] = f2tf32(w.x);
            Bsm[bkk[it]][bq[it]*4+1] = f2tf32(w.y);
            Bsm[bkk[it]][bq[it]*4+2] = f2tf32(w.z);
            Bsm[bkk[it]][bq[it]*4+3] = f2tf32(w.w);
        }
        if (k0 + 32 < K) {
            int kn = k0 + 32;
            #pragma unroll
            for (int it = 0; it < 2; it++) {
                pa[it] = *reinterpret_cast<const float4*>(&A0[(long)(row0+arow[it])*K + kn + akq[it]*4]);
                int c0 = bq[it]*4;
                float4 v;
                v.x = (c0+0 < N) ? Bm[(long)(kn+bkk[it])*N + c0+0] : 0.f;
                v.y = (c0+1 < N) ? Bm[(long)(kn+bkk[it])*N + c0+1] : 0.f;
                v.z = (c0+2 < N) ? Bm[(long)(kn+bkk[it])*N + c0+2] : 0.f;
                v.w = (c0+3 < N) ? Bm[(long)(kn+bkk[it])*N + c0+3] : 0.f;
                pb[it] = v;
            }
        }
        __syncthreads();
        #pragma unroll
        for (int ks = 0; ks < 32; ks += 8) {
            unsigned afr[2][4];
            #pragma unroll
            for (int i = 0; i < 2; i++) {
                int r = warpM*32 + i*16;
                afr[i][0] = Asm[r + g    ][ks + t4    ];
                afr[i][1] = Asm[r + g + 8][ks + t4    ];
                afr[i][2] = Asm[r + g    ][ks + t4 + 4];
                afr[i][3] = Asm[r + g + 8][ks + t4 + 4];
            }
            unsigned bfr[2][2];
            #pragma unroll
            for (int j = 0; j < 2; j++) {
                int nn = warpN*16 + j*8 + g;
                bfr[j][0] = Bsm[ks + t4    ][nn];
                bfr[j][1] = Bsm[ks + t4 + 4][nn];
            }
            #pragma unroll
            for (int i = 0; i < 2; i++)
                #pragma unroll
                for (int j = 0; j < 2; j++)
                    asm volatile(
                        "mma.sync.aligned.m16n8k8.row.col.f32.tf32.tf32.f32 "
                        "{%0,%1,%2,%3}, {%4,%5,%6,%7}, {%8,%9}, {%0,%1,%2,%3};"
                        : "+f"(acc[i][j][0]), "+f"(acc[i][j][1]),
                          "+f"(acc[i][j][2]), "+f"(acc[i][j][3])
                        : "r"(afr[i][0]), "r"(afr[i][1]), "r"(afr[i][2]), "r"(afr[i][3]),
                          "r"(bfr[j][0]), "r"(bfr[j][1]));
        }
        __syncthreads();
    }

    #pragma unroll
    for (int i = 0; i < 2; i++) {
        int r = warpM*32 + i*16 + g;
        #pragma unroll
        for (int j = 0; j < 2; j++) {
            int c = warpN*16 + j*8 + t4*2;
            #pragma unroll
            for (int h = 0; h < 2; h++) {
                int cc = c + h;
                float bb = (cc < N) ? bias[cc] : 0.f;
                Cs[r][cc]   = acc[i][j][h]   + bb;
                Cs[r+8][cc] = acc[i][j][2+h] + bb;
            }
        }
    }
    __syncthreads();

    if (tid < 128) {
        int lrow = tid >> 1, dimc = tid & 1;
        int grow = row0 + lrow;
        float cur = centers[grow*PREV*2 + (PREV-1)*2 + dimc];
        float accum = 0.f;
        #pragma unroll
        for (int p = 0; p < PRED; p++) {
            float v = Cs[lrow][2*p + dimc];
            out[(long)grow*N + 2*p + dimc] = v;
            accum += v;
            out[(long)(ROWS_N)*N + (long)grow*N + 2*p + dimc] = accum + cur;
        }
    }
}

// =======================================================================
// Fused edge GEMM v8: 64 rows x ALL 256 cols in one pass.
// Warp tile 32x64 (acc[2][8][4]), 2 CTAs/SM, 3-stage cp.async B,
// 1 sync/iter, 8 iters total. A fragments loaded once (not per half).
// =======================================================================
#define A_ROWS   64
#define AK_PAD   264
#define A_BYTES  (A_ROWS*AK_PAD*2)        // 33792
#define BSTG_B   (256*40*2)               // 20480 per stage
#define B_BYTES  (3*BSTG_B)               // 61440
#define EDGE_SMEM (A_BYTES + B_BYTES + 1024)

__global__ __launch_bounds__(256, 2)
void edge_gemm2_bf16(const float* __restrict__ xTop, const float* __restrict__ xBot,
                     const float* __restrict__ b1,
                     const __nv_bfloat16* __restrict__ w2t, const float* __restrict__ b2,
                     const int* __restrict__ recv_idx, const int* __restrict__ send_idx,
                     __nv_bfloat16* __restrict__ h2) {
    extern __shared__ char smraw[];
    __nv_bfloat16* Afull = reinterpret_cast<__nv_bfloat16*>(smraw);           // [64][264]
    __nv_bfloat16* Bsn   = reinterpret_cast<__nv_bfloat16*>(smraw + A_BYTES); // [3][256][40]
    int* topBase = reinterpret_cast<int*>(smraw + A_BYTES + B_BYTES);
    int* botBase = topBase + A_ROWS;

    const int tid  = threadIdx.x;
    const int lane = tid & 31;
    const int warp = tid >> 5;
    const int warpM = warp & 1;          // rows warpM*32
    const int warpN = warp >> 1;         // cols warpN*64
    const int row0 = blockIdx.x * A_ROWS;

    if (tid < A_ROWS) {
        int grow = row0 + tid;
        int b = grow / EE;
        int e = grow - b * EE;
        topBase[tid] = (b*NN + recv_idx[e]) * HH;
        botBase[tid] = (b*NN + send_idx[e]) * HH;
    }
    __syncthreads();

    // ---- Phase 1: build A tile (64 rows x 256 k), coalesced ----
    {
        const int kq = tid & 63;
        const int rb = tid >> 6;
        const int kb = kq * 4;
        float4 bb = *reinterpret_cast<const float4*>(&b1[kb]);
        #pragma unroll
        for (int it = 0; it < 16; it++) {
            int row = it*4 + rb;
            float4 a  = *reinterpret_cast<const float4*>(&xTop[topBase[row] + kb]);
            float4 bv = *reinterpret_cast<const float4*>(&xBot[botBase[row] + kb]);
            unsigned p0 = packbf2(elu_ff(a.x + bv.x + bb.x), elu_ff(a.y + bv.y + bb.y));
            unsigned p1 = packbf2(elu_ff(a.z + bv.z + bb.z), elu_ff(a.w + bv.w + bb.w));
            *reinterpret_cast<uint2*>(&Afull[row*AK_PAD + kb]) = make_uint2(p0, p1);
        }
    }

    // B staging tasks: 1024 tasks = 256 n x 4 k-chunks of 16B; 4 per thread
    int bn[4], bkh[4];
    #pragma unroll
    for (int it = 0; it < 4; it++) {
        int task = it*256 + tid;
        bkh[it] = task & 3;
        bn[it]  = task >> 2;
    }

    const int lt  = lane >> 3;
    const int lrw = lane & 7;
    const int mrow0 = warpM * 32;
    const int ncol0 = warpN * 64;
    const uint32_t aBase = smem_u32(Afull);
    const uint32_t bBase0 = smem_u32(Bsn);
    const uint32_t aLanePart = (uint32_t)(mrow0 + (lt & 1)*8 + lrw) * (AK_PAD*2u)
                             + (uint32_t)(lt >> 1) * 16u;
    const uint32_t bLanePart = (uint32_t)(ncol0 + lt*8 + lrw) * 80u;
    uint32_t dstPart[4];
    const __nv_bfloat16* srcB[4];
    #pragma unroll
    for (int it = 0; it < 4; it++) {
        dstPart[it] = (uint32_t)(bn[it]*80 + bkh[it]*16);
        srcB[it] = &w2t[(long)bn[it]*HH + bkh[it]*8];
    }

    __syncthreads();   // A tile ready

    const int g  = lane >> 2;
    const int t4 = lane & 3;

    // prologue: issue B stages 0 and 1
    #pragma unroll
    for (int s = 0; s < 2; s++) {
        #pragma unroll
        for (int it = 0; it < 4; it++)
            CP_ASYNC16(bBase0 + (uint32_t)s*BSTG_B + dstPart[it], srcB[it] + s*32);
        CP_COMMIT();
    }

    float acc[2][8][4] = {};

    #pragma unroll 1
    for (int i = 0; i < 8; i++) {
        const int stg = i - (i >= 3 ? 3 : 0) - (i >= 6 ? 3 : 0);   // i % 3
        if (i < 7) { CP_WAIT(1); } else { CP_WAIT(0); }
        __syncthreads();
        if (i + 2 < 8) {
            int s2 = (i+2) - ((i+2) >= 3 ? 3 : 0) - ((i+2) >= 6 ? 3 : 0);
            #pragma unroll
            for (int it = 0; it < 4; it++)
                CP_ASYNC16(bBase0 + (uint32_t)s2*BSTG_B + dstPart[it], srcB[it] + (i+2)*32);
            CP_COMMIT();
        }

        const uint32_t aCur = aBase + aLanePart + (uint32_t)i * 64u;
        const uint32_t bCur = bBase0 + (uint32_t)stg * BSTG_B + bLanePart;

        #pragma unroll
        for (int ks = 0; ks < 32; ks += 16) {
            unsigned afr[2][4];
            #pragma unroll
            for (int ii = 0; ii < 2; ii++) {
                LDSM4(afr[ii][0], afr[ii][1], afr[ii][2], afr[ii][3],
                      aCur + (uint32_t)ii*(16u*AK_PAD*2u) + (uint32_t)ks*2u);
            }
            unsigned bfr[8][2];
            #pragma unroll
            for (int jb = 0; jb < 2; jb++) {
                #pragma unroll
                for (int kh = 0; kh < 2; kh++) {
                    unsigned t0, t1, t2, t3;
                    LDSM4(t0, t1, t2, t3,
                          bCur + (uint32_t)jb*2560u + (uint32_t)ks*2u + (uint32_t)kh*16u);
                    bfr[jb*4+0][kh] = t0;
                    bfr[jb*4+1][kh] = t1;
                    bfr[jb*4+2][kh] = t2;
                    bfr[jb*4+3][kh] = t3;
                }
            }
            #pragma unroll
            for (int j = 0; j < 8; j++) {
                #pragma unroll
                for (int ii = 0; ii < 2; ii++)
                    asm volatile(
                        "mma.sync.aligned.m16n8k16.row.col.f32.bf16.bf16.f32 "
                        "{%0,%1,%2,%3}, {%4,%5,%6,%7}, {%8,%9}, {%0,%1,%2,%3};"
                        : "+f"(acc[ii][j][0]), "+f"(acc[ii][j][1]),
                          "+f"(acc[ii][j][2]), "+f"(acc[ii][j][3])
                        : "r"(afr[ii][0]), "r"(afr[ii][1]), "r"(afr[ii][2]), "r"(afr[ii][3]),
                          "r"(bfr[j][0]), "r"(bfr[j][1]));
            }
        }
    }

    // epilogue: bias + elu -> bf16 packed stores (full 256 cols)
    #pragma unroll
    for (int i = 0; i < 2; i++) {
        int r_lo = row0 + mrow0 + i*16 + g;
        #pragma unroll
        for (int j = 0; j < 8; j++) {
            int c = ncol0 + j*8 + t4*2;
            float bb0 = b2[c], bb1 = b2[c+1];
            *reinterpret_cast<unsigned*>(&h2[(long)r_lo*HH + c]) =
                packbf2(elu_ff(acc[i][j][0] + bb0), elu_ff(acc[i][j][1] + bb1));
            *reinterpret_cast<unsigned*>(&h2[(long)(r_lo+8)*HH + c]) =
                packbf2(elu_ff(acc[i][j][2] + bb0), elu_ff(acc[i][j][3] + bb1));
        }
    }
}

// ---------------- vectorized per-node gather sums (bf16 h2) ----------------
__global__ void scatter_kernel(const __nv_bfloat16* __restrict__ h2,
                               const int* __restrict__ list_rec, const int* __restrict__ cnt_rec,
                               const int* __restrict__ list_send, const int* __restrict__ cnt_send,
                               float* __restrict__ inc_raw, float* __restrict__ sq_part,
                               float* __restrict__ out_raw) {
    int id = blockIdx.x;
    bool isOut = id >= ROWS_N;
    int bn = id & (ROWS_N-1);
    int b = bn >> 6, n = bn & 63;
    const int tid = threadIdx.x;
    const int c4 = tid & 63;
    const int rs = tid >> 6;
    const int* __restrict__ list = (isOut ? list_send : list_rec) + n*EE;
    const int cnt = (isOut ? cnt_send : cnt_rec)[n];

    float4 acc = make_float4(0.f, 0.f, 0.f, 0.f);
    float4 asq = make_float4(0.f, 0.f, 0.f, 0.f);
    for (int k = rs; k < cnt; k += 4) {
        int e = list[k];
        uint2 u = *reinterpret_cast<const uint2*>(&h2[(long)(b*EE + e)*HH + c4*4]);
        __nv_bfloat162 p0 = *reinterpret_cast<__nv_bfloat162*>(&u.x);
        __nv_bfloat162 p1 = *reinterpret_cast<__nv_bfloat162*>(&u.y);
        float v0 = __bfloat162float(p0.x), v1 = __bfloat162float(p0.y);
        float v2 = __bfloat162float(p1.x), v3 = __bfloat162float(p1.y);
        acc.x += v0; acc.y += v1; acc.z += v2; acc.w += v3;
        if (!isOut) {
            asq.x += v0*v0; asq.y += v1*v1; asq.z += v2*v2; asq.w += v3*v3;
        }
    }
    __shared__ float4 sa[4][64];
    __shared__ float4 sq[4][64];
    sa[rs][c4] = acc;
    if (!isOut) sq[rs][c4] = asq;
    __syncthreads();
    if (rs == 0) {
        float4 t = sa[0][c4];
        #pragma unroll
        for (int r = 1; r < 4; r++) {
            float4 u = sa[r][c4];
            t.x += u.x; t.y += u.y; t.z += u.z; t.w += u.w;
        }
        if (!isOut) {
            float4 s = sq[0][c4];
            #pragma unroll
            for (int r = 1; r < 4; r++) {
                float4 u = sq[r][c4];
                s.x += u.x; s.y += u.y; s.z += u.z; s.w += u.w;
            }
            *reinterpret_cast<float4*>(&inc_raw[bn*HH + c4*4]) = t;
            *reinterpret_cast<float4*>(&sq_part[bn*HH + c4*4]) = s;
        } else {
            *reinterpret_cast<float4*>(&out_raw[bn*HH + c4*4]) = t;
        }
    }
}

// ---------------- BN stats -> affine (a,c) ----------------
template<bool SRC_SQ>
__global__ void stats_kernel(const float* __restrict__ sum_part, const float* __restrict__ sq_part,
                             const float* __restrict__ gamma, const float* __restrict__ beta,
                             float* __restrict__ a, float* __restrict__ c,
                             int nrows, float count) {
    int h = blockIdx.x;
    float s = 0.f, sq = 0.f;
    for (int r = threadIdx.x; r < nrows; r += 256) {
        float v = sum_part[r*HH + h];
        s += v;
        if (SRC_SQ) sq += v*v; else sq += sq_part[r*HH + h];
    }
    __shared__ float ss[256], ssq[256];
    ss[threadIdx.x] = s; ssq[threadIdx.x] = sq;
    __syncthreads();
    for (int st = 128; st > 0; st >>= 1) {
        if (threadIdx.x < st) { ss[threadIdx.x] += ss[threadIdx.x+st]; ssq[threadIdx.x] += ssq[threadIdx.x+st]; }
        __syncthreads();
    }
    if (threadIdx.x == 0) {
        float mu = ss[0] / count;
        float var = ssq[0] / count - mu*mu;
        float av = gamma[h] * rsqrtf(var + 1e-5f);
        a[h] = av;
        c[h] = beta[h] - mu * av;
    }
}

// ---------------- launcher ----------------
extern "C" void kernel_launch(void* const* d_in, const int* in_sizes, int n_in,
                              void* d_out, int out_size) {
    const float* centers  = (const float*)d_in[0];
    const float* rel_rec  = (const float*)d_in[1];
    const float* rel_send = (const float*)d_in[2];
    const float* W_traj   = (const float*)d_in[3];
    const float* b_traj   = (const float*)d_in[4];
    const float* n2e_W1   = (const float*)d_in[5];
    const float* n2e_b1   = (const float*)d_in[6];
    const float* n2e_W2   = (const float*)d_in[7];
    const float* n2e_b2   = (const float*)d_in[8];
    const float* n2e_g    = (const float*)d_in[9];
    const float* n2e_be   = (const float*)d_in[10];
    const float* e2n_W1   = (const float*)d_in[11];
    const float* e2n_b1   = (const float*)d_in[12];
    const float* e2n_W2   = (const float*)d_in[13];
    const float* e2n_b2   = (const float*)d_in[14];
    const float* e2n_g    = (const float*)d_in[15];
    const float* e2n_be   = (const float*)d_in[16];
    const float* W_fuse   = (const float*)d_in[17];
    const float* b_fuse   = (const float*)d_in[18];
    const float* W_pred   = (const float*)d_in[19];
    const float* b_pred   = (const float*)d_in[20];
    float* out = (float*)d_out;

    float *p_x, *p_xTop, *p_xBot, *p_inc, *p_incsq, *p_outg;
    float *p_nh1, *p_mraw, *p_fused;
    float *p_ae, *p_ce, *p_an, *p_cn, *p_idr, *p_ids;
    int *p_recv, *p_send, *p_lr, *p_ls, *p_cr, *p_cs;
    __nv_bfloat16 *p_w2t, *p_h2;
    cudaGetSymbolAddress((void**)&p_x, d_x);
    cudaGetSymbolAddress((void**)&p_xTop, d_xTop);
    cudaGetSymbolAddress((void**)&p_xBot, d_xBot);
    cudaGetSymbolAddress((void**)&p_h2, d_h2);
    cudaGetSymbolAddress((void**)&p_inc, d_inc);
    cudaGetSymbolAddress((void**)&p_incsq, d_incsq);
    cudaGetSymbolAddress((void**)&p_outg, d_outg);
    cudaGetSymbolAddress((void**)&p_nh1, d_nh1);
    cudaGetSymbolAddress((void**)&p_mraw, d_mraw);
    cudaGetSymbolAddress((void**)&p_fused, d_fused);
    cudaGetSymbolAddress((void**)&p_ae, d_ae);
    cudaGetSymbolAddress((void**)&p_ce, d_ce);
    cudaGetSymbolAddress((void**)&p_an, d_an);
    cudaGetSymbolAddress((void**)&p_cn, d_cn);
    cudaGetSymbolAddress((void**)&p_idr, d_invdegrec);
    cudaGetSymbolAddress((void**)&p_ids, d_invdegsend);
    cudaGetSymbolAddress((void**)&p_recv, d_recv);
    cudaGetSymbolAddress((void**)&p_send, d_send);
    cudaGetSymbolAddress((void**)&p_lr, d_listrec);
    cudaGetSymbolAddress((void**)&p_ls, d_listsend);
    cudaGetSymbolAddress((void**)&p_cr, d_cntrec);
    cudaGetSymbolAddress((void**)&p_cs, d_cntsend);
    cudaGetSymbolAddress((void**)&p_w2t, d_w2t);

    cudaFuncSetAttribute(edge_gemm2_bf16, cudaFuncAttributeMaxDynamicSharedMemorySize, EDGE_SMEM);
    cudaFuncSetAttribute(mma_gemm_v3<0,false>, cudaFuncAttributeMaxDynamicSharedMemorySize, GEMM_SMEM);
    cudaFuncSetAttribute(mma_gemm_v3<1,true>,  cudaFuncAttributeMaxDynamicSharedMemorySize, GEMM_SMEM);
    cudaFuncSetAttribute(mma_gemm_v3<0,true>,  cudaFuncAttributeMaxDynamicSharedMemorySize, GEMM_SMEM);
    cudaFuncSetAttribute(mma_gemm_v3<2,false>, cudaFuncAttributeMaxDynamicSharedMemorySize, GEMM_SMEM);

    // 1. fused prep: derive + traj + W2^T + per-node lists
    prep_kernel<<<16 + ROWS_N + HH + 128, HH>>>(rel_rec, rel_send, p_recv, p_send,
                                                centers, W_traj, b_traj, n2e_W2, p_w2t, p_x,
                                                p_lr, p_ls, p_cr, p_cs, p_idr, p_ids);

    // 2. xTop/xBot (dual-output, K-step 64)
    mma_gemm_v3<0,false><<<dim3(HH/64, ROWS_N/64, 2), 256, GEMM_SMEM>>>(
        p_x, nullptr, nullptr, nullptr, nullptr, nullptr,
        n2e_W1, n2e_W1 + HH*HH, nullptr, p_xTop, p_xBot, ROWS_N, HH, HH);

    // 3. fused edge MLP v8 (single-pass 256 cols)
    edge_gemm2_bf16<<<ROWS_E/A_ROWS, 256, EDGE_SMEM>>>(p_xTop, p_xBot, n2e_b1,
                                                       p_w2t, n2e_b2,
                                                       p_recv, p_send, p_h2);

    // 4. scatter sums + edge BN stats
    scatter_kernel<<<2*ROWS_N, 256>>>(p_h2, p_lr, p_cr, p_ls, p_cs, p_inc, p_incsq, p_outg);
    stats_kernel<false><<<HH, 256>>>(p_inc, p_incsq, n2e_g, n2e_be, p_ae, p_ce, ROWS_N, (float)ROWS_E);

    // 5. node MLP (K-step 64)
    mma_gemm_v3<1,true><<<dim3(HH/64, ROWS_N/64, 1), 256, GEMM_SMEM>>>(
        p_inc, p_outg, p_ae, p_ce, p_idr, p_ids,
        e2n_W1, e2n_W1, e2n_b1, p_nh1, p_nh1, ROWS_N, HH, 2*HH);
    mma_gemm_v3<0,true><<<dim3(HH/64, ROWS_N/64, 1), 256, GEMM_SMEM>>>(
        p_nh1, nullptr, nullptr, nullptr, nullptr, nullptr,
        e2n_W2, e2n_W2, e2n_b2, p_mraw, p_mraw, ROWS_N, HH, HH);
    stats_kernel<true><<<HH, 256>>>(p_mraw, nullptr, e2n_g, e2n_be, p_an, p_cn, ROWS_N, (float)ROWS_N);

    // 6. fuse + predict (+ fused cumsum epilogue)
    mma_gemm_v3<2,false><<<dim3(HH/64, ROWS_N/64, 1), 256, GEMM_SMEM>>>(
        p_x, p_mraw, p_an, p_cn, nullptr, nullptr,
        W_fuse, W_fuse, b_fuse, p_fused, p_fused, ROWS_N, HH, 2*HH);
    pred_pos_kernel<<<dim3(1, ROWS_N/64), 256>>>(p_fused, W_pred, b_pred, centers, out);
}

// round 16
// speedup vs baseline: 1.0554x; 1.0554x over previous
#include <cuda_runtime.h>
#include <cuda_bf16.h>
#include <math.h>
#include <stdint.h>

#define BB   16
#define NN   64
#define PREV 6
#define PRED 30
#define HH   256
#define EE   (NN*(NN-1))      // 4032
#define ROWS_E (BB*EE)        // 64512
#define ROWS_N (BB*NN)        // 1024

// ---------------- static scratch ----------------
__device__ float d_x[ROWS_N*HH];
__device__ float d_xTop[ROWS_N*HH];
__device__ float d_xBot[ROWS_N*HH];
__device__ __nv_bfloat16 d_h2[ROWS_E*HH];     // h2 bf16
__device__ float d_inc[ROWS_N*HH];
__device__ float d_incsq[ROWS_N*HH];
__device__ float d_outg[ROWS_N*HH];
__device__ float d_nh1[ROWS_N*HH];
__device__ float d_mraw[ROWS_N*HH];
__device__ float d_fused[ROWS_N*HH];
__device__ float d_ae[HH], d_ce[HH], d_an[HH], d_cn[HH];
__device__ int   d_recv[EE], d_send[EE];
__device__ int   d_listrec[NN*EE], d_listsend[NN*EE];
__device__ int   d_cntrec[NN], d_cntsend[NN];
__device__ float d_invdegrec[NN], d_invdegsend[NN];
__device__ __nv_bfloat16 d_w2t[HH*HH];   // W2^T in bf16: [n][k]

__device__ __forceinline__ float elu_f(float x)  { return x > 0.f ? x : (expf(x) - 1.f); }
__device__ __forceinline__ float elu_ff(float x) { return x > 0.f ? x : (__expf(x) - 1.f); }

__device__ __forceinline__ unsigned f2tf32(float x) {
    unsigned r;
    asm("cvt.rna.tf32.f32 %0, %1;" : "=r"(r) : "f"(x));
    return r;
}
__device__ __forceinline__ unsigned packbf2(float lo, float hi) {
    __nv_bfloat162 v = __floats2bfloat162_rn(lo, hi);
    return *reinterpret_cast<unsigned*>(&v);
}
__device__ __forceinline__ uint32_t smem_u32(const void* p) {
    uint32_t a;
    asm("{ .reg .u64 t; cvta.to.shared.u64 t, %1; cvt.u32.u64 %0, t; }" : "=r"(a) : "l"(p));
    return a;
}

#define LDSM4(r0,r1,r2,r3,addr) \
    asm volatile("ldmatrix.sync.aligned.m8n8.x4.shared.b16 {%0,%1,%2,%3}, [%4];" \
        : "=r"(r0), "=r"(r1), "=r"(r2), "=r"(r3) : "r"(addr))

#define CP_ASYNC16(dst, src) \
    asm volatile("cp.async.ca.shared.global [%0], [%1], 16;" :: "r"(dst), "l"(src) : "memory")
#define CP_COMMIT() asm volatile("cp.async.commit_group;" ::: "memory")
#define CP_WAIT(n)  asm volatile("cp.async.wait_group %0;" :: "n"(n) : "memory")

// ---------------- fused prep: derive + traj + W2^T + per-node lists ----------------
__global__ void prep_kernel(const float* __restrict__ rel_rec,
                            const float* __restrict__ rel_send,
                            int* __restrict__ recv_idx, int* __restrict__ send_idx,
                            const float* __restrict__ centers,
                            const float* __restrict__ W, const float* __restrict__ bias,
                            const float* __restrict__ W2, __nv_bfloat16* __restrict__ w2t,
                            float* __restrict__ x,
                            int* __restrict__ list_rec, int* __restrict__ list_send,
                            int* __restrict__ cnt_rec, int* __restrict__ cnt_send,
                            float* __restrict__ invdeg_rec, float* __restrict__ invdeg_send) {
    if (blockIdx.x < 16) {
        int e = blockIdx.x * 256 + threadIdx.x;
        if (e >= EE) return;
        int r = 0, s = 0; float br = -1.f, bs = -1.f;
        for (int n = 0; n < NN; n++) {
            float vr = rel_rec[e*NN + n];
            float vs = rel_send[e*NN + n];
            if (vr > br) { br = vr; r = n; }
            if (vs > bs) { bs = vs; s = n; }
        }
        recv_idx[e] = r; send_idx[e] = s;
        return;
    }
    if (blockIdx.x >= 1296) {
        int id = blockIdx.x - 1296;
        if (threadIdx.x >= 64) return;
        const bool isSend = id >= NN;
        const int n = id & (NN-1);
        const float* __restrict__ oneHot = (isSend ? rel_send : rel_rec);
        int* __restrict__ list = (isSend ? list_send : list_rec) + n*EE;
        const int t = threadIdx.x;
        const int CH = EE / 64;
        const int base = t * CH;
        int c = 0;
        for (int i = 0; i < CH; i++) c += (oneHot[(base+i)*NN + n] > 0.5f) ? 1 : 0;
        __shared__ int pre[64];
        pre[t] = c;
        __syncthreads();
        for (int off = 1; off < 64; off <<= 1) {
            int v = (t >= off) ? pre[t-off] : 0;
            __syncthreads();
            pre[t] += v;
            __syncthreads();
        }
        int offset = pre[t] - c;
        for (int i = 0; i < CH; i++) {
            int e = base + i;
            if (oneHot[e*NN + n] > 0.5f) list[offset++] = e;
        }
        if (t == 63) {
            int tot = pre[63];
            float iv = tot ? 1.f/(float)tot : 1.f;
            if (isSend) { cnt_send[n] = tot; invdeg_send[n] = iv; }
            else        { cnt_rec[n]  = tot; invdeg_rec[n]  = iv; }
        }
        return;
    }
    if (blockIdx.x >= 16 + ROWS_N) {
        int n = blockIdx.x - 16 - ROWS_N;
        int k = threadIdx.x;
        w2t[n*HH + k] = __float2bfloat16(W2[k*HH + n]);
        return;
    }
    int row = blockIdx.x - 16;
    int h = threadIdx.x;
    __shared__ float rp[PREV*2];
    if (h < PREV*2) {
        int p = h >> 1, c = h & 1;
        float v = 0.f;
        if (p > 0) v = centers[row*PREV*2 + p*2 + c] - centers[row*PREV*2 + (p-1)*2 + c];
        rp[h] = v;
    }
    __syncthreads();
    float acc = bias[h];
    #pragma unroll
    for (int k = 0; k < PREV*2; k++) acc += rp[k] * W[k*HH + h];
    x[row*HH + h] = acc;
}

// =======================================================================
// Small-GEMM v3: K-step 64 (unchanged from R14 passing version)
// =======================================================================
#define GEMM_SMEM ((2*64*68 + 2*64*72)*4)

template<int AMODE, bool ELU>
__global__ __launch_bounds__(256)
void mma_gemm_v3(const float* __restrict__ A0, const float* __restrict__ A1,
                 const float* __restrict__ aVec, const float* __restrict__ cVec,
                 const float* __restrict__ invDegR, const float* __restrict__ invDegS,
                 const float* __restrict__ B0, const float* __restrict__ B1,
                 const float* __restrict__ bias,
                 float* __restrict__ C0, float* __restrict__ C1,
                 int M, int N, int K) {
    const float* __restrict__ Bm = (blockIdx.z == 0) ? B0 : B1;
    float* __restrict__ C = (blockIdx.z == 0) ? C0 : C1;

    extern __shared__ float gsm[];
    float* Asm = gsm;                       // [2][64][68]
    float* Bsm = gsm + 2*64*68;             // [2][64][72]

    const int tid  = threadIdx.x;
    const int lane = tid & 31;
    const int warp = tid >> 5;
    const int warpM = warp & 1;
    const int warpN = warp >> 1;
    const int g  = lane >> 2;
    const int t4 = lane & 3;
    const int row0 = blockIdx.y * 64;
    const int col0 = blockIdx.x * 64;

    int arow[4], akq[4], bkk[4], bq[4];
    #pragma unroll
    for (int it = 0; it < 4; it++) {
        int ta = it*256 + tid;
        akq[it] = ta & 15;  arow[it] = ta >> 4;
        bq[it]  = ta & 15;  bkk[it]  = ta >> 4;
    }

    float4 pa[4], pb[4];

    auto prefetch = [&](int k0) {
        #pragma unroll
        for (int it = 0; it < 4; it++) {
            int gk = k0 + akq[it]*4;
            if (AMODE == 0) {
                pa[it] = *reinterpret_cast<const float4*>(&A0[(long)(row0+arow[it])*K + gk]);
            } else {
                const float* src = (gk >= HH) ? A1 : A0;
                pa[it] = *reinterpret_cast<const float4*>(&src[(long)(row0+arow[it])*HH + (gk & (HH-1))]);
            }
            int c0 = col0 + bq[it]*4;
            pb[it] = *reinterpret_cast<const float4*>(&Bm[(long)(k0+bkk[it])*N + c0]);
        }
    };

    auto store = [&](int s, int k0) {
        #pragma unroll
        for (int it = 0; it < 4; it++) {
            int gk = k0 + akq[it]*4;
            float4 v = pa[it];
            if (AMODE == 1) {
                int col = gk & (HH-1);
                float invd = ((gk >= HH) ? invDegS : invDegR)[(row0+arow[it]) & (NN-1)];
                float4 a4 = *reinterpret_cast<const float4*>(&aVec[col]);
                float4 c4 = *reinterpret_cast<const float4*>(&cVec[col]);
                v.x = a4.x*(v.x*invd)+c4.x; v.y = a4.y*(v.y*invd)+c4.y;
                v.z = a4.z*(v.z*invd)+c4.z; v.w = a4.w*(v.w*invd)+c4.w;
            } else if (AMODE == 2) {
                if (gk >= HH) {
                    int col = gk & (HH-1);
                    float4 a4 = *reinterpret_cast<const float4*>(&aVec[col]);
                    float4 c4 = *reinterpret_cast<const float4*>(&cVec[col]);
                    v.x = a4.x*v.x+c4.x; v.y = a4.y*v.y+c4.y;
                    v.z = a4.z*v.z+c4.z; v.w = a4.w*v.w+c4.w;
                }
            }
            float* ap = &Asm[(s*64 + arow[it])*68 + akq[it]*4];
            reinterpret_cast<unsigned*>(ap)[0] = f2tf32(v.x);
            reinterpret_cast<unsigned*>(ap)[1] = f2tf32(v.y);
            reinterpret_cast<unsigned*>(ap)[2] = f2tf32(v.z);
            reinterpret_cast<unsigned*>(ap)[3] = f2tf32(v.w);

            float4 w = pb[it];
            float* bp = &Bsm[(s*64 + bkk[it])*72 + bq[it]*4];
            reinterpret_cast<unsigned*>(bp)[0] = f2tf32(w.x);
            reinterpret_cast<unsigned*>(bp)[1] = f2tf32(w.y);
            reinterpret_cast<unsigned*>(bp)[2] = f2tf32(w.z);
            reinterpret_cast<unsigned*>(bp)[3] = f2tf32(w.w);
        }
    };

    float acc[2][2][4] = {};
    const int nIter = K >> 6;

    prefetch(0);
    store(0, 0);
    __syncthreads();

    for (int i = 0; i < nIter; i++) {
        int cur = i & 1;
        if (i + 1 < nIter) prefetch((i+1) * 64);

        const unsigned* Ac = reinterpret_cast<const unsigned*>(&Asm[(cur*64)*68]);
        const unsigned* Bc = reinterpret_cast<const unsigned*>(&Bsm[(cur*64)*72]);

        #pragma unroll
        for (int ks = 0; ks < 64; ks += 8) {
            unsigned afr[2][4];
            #pragma unroll
            for (int ii = 0; ii < 2; ii++) {
                int r = warpM*32 + ii*16;
                afr[ii][0] = Ac[(r + g    )*68 + ks + t4    ];
                afr[ii][1] = Ac[(r + g + 8)*68 + ks + t4    ];
                afr[ii][2] = Ac[(r + g    )*68 + ks + t4 + 4];
                afr[ii][3] = Ac[(r + g + 8)*68 + ks + t4 + 4];
            }
            unsigned bfr[2][2];
            #pragma unroll
            for (int j = 0; j < 2; j++) {
                int nn = warpN*16 + j*8 + g;
                bfr[j][0] = Bc[(ks + t4    )*72 + nn];
                bfr[j][1] = Bc[(ks + t4 + 4)*72 + nn];
            }
            #pragma unroll
            for (int ii = 0; ii < 2; ii++)
                #pragma unroll
                for (int j = 0; j < 2; j++)
                    asm volatile(
                        "mma.sync.aligned.m16n8k8.row.col.f32.tf32.tf32.f32 "
                        "{%0,%1,%2,%3}, {%4,%5,%6,%7}, {%8,%9}, {%0,%1,%2,%3};"
                        : "+f"(acc[ii][j][0]), "+f"(acc[ii][j][1]),
                          "+f"(acc[ii][j][2]), "+f"(acc[ii][j][3])
                        : "r"(afr[ii][0]), "r"(afr[ii][1]), "r"(afr[ii][2]), "r"(afr[ii][3]),
                          "r"(bfr[j][0]), "r"(bfr[j][1]));
        }
        if (i + 1 < nIter) store(cur ^ 1, (i+1) * 64);
        __syncthreads();
    }

    #pragma unroll
    for (int i = 0; i < 2; i++) {
        int r = row0 + warpM*32 + i*16 + g;
        #pragma unroll
        for (int j = 0; j < 2; j++) {
            int c = col0 + warpN*16 + j*8 + t4*2;
            #pragma unroll
            for (int h = 0; h < 2; h++) {
                int cc = c + h;
                float bb = bias ? bias[cc] : 0.f;
                float v0 = acc[i][j][h]   + bb;
                float v1 = acc[i][j][2+h] + bb;
                if (ELU) { v0 = elu_f(v0); v1 = elu_f(v1); }
                C[(long)r*N + cc]     = v0;
                C[(long)(r+8)*N + cc] = v1;
            }
        }
    }
}

// =======================================================================
// Pred GEMM + cumsum epilogue (unchanged)
// =======================================================================
__global__ __launch_bounds__(256)
void pred_pos_kernel(const float* __restrict__ A0, const float* __restrict__ Bm,
                     const float* __restrict__ bias, const float* __restrict__ centers,
                     float* __restrict__ out) {
    const int N = PRED*2;
    const int K = HH;
    __shared__ unsigned Asm[64][36];
    __shared__ unsigned Bsm[32][72];
    __shared__ float Cs[64][64];
    const int tid  = threadIdx.x;
    const int lane = tid & 31;
    const int warp = tid >> 5;
    const int warpM = warp & 1;
    const int warpN = warp >> 1;
    const int g  = lane >> 2;
    const int t4 = lane & 3;
    const int row0 = blockIdx.y * 64;

    int arow[2], akq[2], bkk[2], bq[2];
    #pragma unroll
    for (int it = 0; it < 2; it++) {
        int ta = it*256 + tid;
        akq[it] = ta & 7;  arow[it] = ta >> 3;
        bkk[it] = ta >> 4; bq[it]  = ta & 15;
    }
    float4 pa[2], pb[2];
    #pragma unroll
    for (int it = 0; it < 2; it++) {
        pa[it] = *reinterpret_cast<const float4*>(&A0[(long)(row0+arow[it])*K + akq[it]*4]);
        int c0 = bq[it]*4;
        float4 v;
        v.x = (c0+0 < N) ? Bm[(long)bkk[it]*N + c0+0] : 0.f;
        v.y = (c0+1 < N) ? Bm[(long)bkk[it]*N + c0+1] : 0.f;
        v.z = (c0+2 < N) ? Bm[(long)bkk[it]*N + c0+2] : 0.f;
        v.w = (c0+3 < N) ? Bm[(long)bkk[it]*N + c0+3] : 0.f;
        pb[it] = v;
    }

    float acc[2][2][4] = {};
    for (int k0 = 0; k0 < K; k0 += 32) {
        #pragma unroll
        for (int it = 0; it < 2; it++) {
            float4 v = pa[it];
            Asm[arow[it]][akq[it]*4+0] = f2tf32(v.x);
            Asm[arow[it]][akq[it]*4+1] = f2tf32(v.y);
            Asm[arow[it]][akq[it]*4+2] = f2tf32(v.z);
            Asm[arow[it]][akq[it]*4+3] = f2tf32(v.w);
            float4 w = pb[it];
            Bsm[bkk[it]][bq[it]*4+0] = f2tf32(w.x);
            Bsm[bkk[it]][bq[it]*4+1] = f2tf32(w.y);
            Bsm[bkk[it]][bq[it]*4+2] = f2tf32(w.z);
            Bsm[bkk[it]][bq[it]*4+3] = f2tf32(w.w);
        }
        if (k0 + 32 < K) {
            int kn = k0 + 32;
            #pragma unroll
            for (int it = 0; it < 2; it++) {
                pa[it] = *reinterpret_cast<const float4*>(&A0[(long)(row0+arow[it])*K + kn + akq[it]*4]);
                int c0 = bq[it]*4;
                float4 v;
                v.x = (c0+0 < N) ? Bm[(long)(kn+bkk[it])*N + c0+0] : 0.f;
                v.y = (c0+1 < N) ? Bm[(long)(kn+bkk[it])*N + c0+1] : 0.f;
                v.z = (c0+2 < N) ? Bm[(long)(kn+bkk[it])*N + c0+2] : 0.f;
                v.w = (c0+3 < N) ? Bm[(long)(kn+bkk[it])*N + c0+3] : 0.f;
                pb[it] = v;
            }
        }
        __syncthreads();
        #pragma unroll
        for (int ks = 0; ks < 32; ks += 8) {
            unsigned afr[2][4];
            #pragma unroll
            for (int i = 0; i < 2; i++) {
                int r = warpM*32 + i*16;
                afr[i][0] = Asm[r + g    ][ks + t4    ];
                afr[i][1] = Asm[r + g + 8][ks + t4    ];
                afr[i][2] = Asm[r + g    ][ks + t4 + 4];
                afr[i][3] = Asm[r + g + 8][ks + t4 + 4];
            }
            unsigned bfr[2][2];
            #pragma unroll
            for (int j = 0; j < 2; j++) {
                int nn = warpN*16 + j*8 + g;
                bfr[j][0] = Bsm[ks + t4    ][nn];
                bfr[j][1] = Bsm[ks + t4 + 4][nn];
            }
            #pragma unroll
            for (int i = 0; i < 2; i++)
                #pragma unroll
                for (int j = 0; j < 2; j++)
                    asm volatile(
                        "mma.sync.aligned.m16n8k8.row.col.f32.tf32.tf32.f32 "
                        "{%0,%1,%2,%3}, {%4,%5,%6,%7}, {%8,%9}, {%0,%1,%2,%3};"
                        : "+f"(acc[i][j][0]), "+f"(acc[i][j][1]),
                          "+f"(acc[i][j][2]), "+f"(acc[i][j][3])
                        : "r"(afr[i][0]), "r"(afr[i][1]), "r"(afr[i][2]), "r"(afr[i][3]),
                          "r"(bfr[j][0]), "r"(bfr[j][1]));
        }
        __syncthreads();
    }

    #pragma unroll
    for (int i = 0; i < 2; i++) {
        int r = warpM*32 + i*16 + g;
        #pragma unroll
        for (int j = 0; j < 2; j++) {
            int c = warpN*16 + j*8 + t4*2;
            #pragma unroll
            for (int h = 0; h < 2; h++) {
                int cc = c + h;
                float bb = (cc < N) ? bias[cc] : 0.f;
                Cs[r][cc]   = acc[i][j][h]   + bb;
                Cs[r+8][cc] = acc[i][j][2+h] + bb;
            }
        }
    }
    __syncthreads();

    if (tid < 128) {
        int lrow = tid >> 1, dimc = tid & 1;
        int grow = row0 + lrow;
        float cur = centers[grow*PREV*2 + (PREV-1)*2 + dimc];
        float accum = 0.f;
        #pragma unroll
        for (int p = 0; p < PRED; p++) {
            float v = Cs[lrow][2*p + dimc];
            out[(long)grow*N + 2*p + dimc] = v;
            accum += v;
            out[(long)(ROWS_N)*N + (long)grow*N + 2*p + dimc] = accum + cur;
        }
    }
}

// =======================================================================
// Fused edge GEMM v7b: 64-row CTAs, 3/SM, 3-stage cp.async B, 1 sync/iter.
// Half-0 B prologue hoisted BEFORE A-build so DMA overlaps gather+ELU.
// =======================================================================
#define A_ROWS   64
#define AK_PAD   264
#define A_BYTES  (A_ROWS*AK_PAD*2)        // 33792
#define B_BYTES  (3*128*40*2)             // 30720 (3 stages)
#define EDGE_SMEM (A_BYTES + B_BYTES + 1024)

__global__ __launch_bounds__(256, 3)
void edge_gemm2_bf16(const float* __restrict__ xTop, const float* __restrict__ xBot,
                     const float* __restrict__ b1,
                     const __nv_bfloat16* __restrict__ w2t, const float* __restrict__ b2,
                     const int* __restrict__ recv_idx, const int* __restrict__ send_idx,
                     __nv_bfloat16* __restrict__ h2) {
    extern __shared__ char smraw[];
    __nv_bfloat16* Afull = reinterpret_cast<__nv_bfloat16*>(smraw);
    __nv_bfloat16* Bsn   = reinterpret_cast<__nv_bfloat16*>(smraw + A_BYTES);
    int* topBase = reinterpret_cast<int*>(smraw + A_BYTES + B_BYTES);
    int* botBase = topBase + A_ROWS;

    const int tid  = threadIdx.x;
    const int lane = tid & 31;
    const int warp = tid >> 5;
    const int warpM = warp & 1;
    const int warpN = warp >> 1;
    const int row0 = blockIdx.x * A_ROWS;

    // B staging task assignment (needed before prologue)
    int bn[2], bkh[2];
    #pragma unroll
    for (int it = 0; it < 2; it++) {
        int task = it*256 + tid;
        bkh[it] = task & 3;
        bn[it]  = task >> 2;
    }
    const uint32_t bBase0 = smem_u32(Bsn);
    const uint32_t BSTG = 128u * 40u * 2u;
    uint32_t dstPart[2];
    #pragma unroll
    for (int it = 0; it < 2; it++) dstPart[it] = (uint32_t)(bn[it]*80 + bkh[it]*16);

    // ---- hoisted half-0 B prologue: overlaps the A-build below ----
    {
        #pragma unroll
        for (int s = 0; s < 2; s++) {
            #pragma unroll
            for (int it = 0; it < 2; it++)
                CP_ASYNC16(bBase0 + (uint32_t)s*BSTG + dstPart[it],
                           &w2t[(long)bn[it]*HH + bkh[it]*8] + s*32);
            CP_COMMIT();
        }
    }

    if (tid < A_ROWS) {
        int grow = row0 + tid;
        int b = grow / EE;
        int e = grow - b * EE;
        topBase[tid] = (b*NN + recv_idx[e]) * HH;
        botBase[tid] = (b*NN + send_idx[e]) * HH;
    }
    __syncthreads();

    // ---- Phase 1: build A tile (64 rows x 256 k), coalesced ----
    {
        const int kq = tid & 63;
        const int rb = tid >> 6;
        const int kb = kq * 4;
        float4 bb = *reinterpret_cast<const float4*>(&b1[kb]);
        #pragma unroll
        for (int it = 0; it < 16; it++) {
            int row = it*4 + rb;
            float4 a  = *reinterpret_cast<const float4*>(&xTop[topBase[row] + kb]);
            float4 bv = *reinterpret_cast<const float4*>(&xBot[botBase[row] + kb]);
            unsigned p0 = packbf2(elu_ff(a.x + bv.x + bb.x), elu_ff(a.y + bv.y + bb.y));
            unsigned p1 = packbf2(elu_ff(a.z + bv.z + bb.z), elu_ff(a.w + bv.w + bb.w));
            *reinterpret_cast<uint2*>(&Afull[row*AK_PAD + kb]) = make_uint2(p0, p1);
        }
    }

    const int lt  = lane >> 3;
    const int lrw = lane & 7;
    const int mrow0 = warpM * 32;
    const int ncol0 = warpN * 32;
    const uint32_t aBase = smem_u32(Afull);
    const uint32_t aLanePart = (uint32_t)(mrow0 + (lt & 1)*8 + lrw) * (AK_PAD*2u)
                             + (uint32_t)(lt >> 1) * 16u;
    const uint32_t bLanePart = (uint32_t)(ncol0 + lt*8 + lrw) * 80u;

    __syncthreads();   // A tile ready

    const int g  = lane >> 2;
    const int t4 = lane & 3;

    #pragma unroll 1
    for (int half = 0; half < 2; half++) {
        const int col0 = half * 128;
        const __nv_bfloat16* srcB[2];
        #pragma unroll
        for (int it = 0; it < 2; it++)
            srcB[it] = &w2t[(long)(col0 + bn[it])*HH + bkh[it]*8];

        // half-1 prologue (half-0's was hoisted before A build)
        if (half == 1) {
            #pragma unroll
            for (int s = 0; s < 2; s++) {
                #pragma unroll
                for (int it = 0; it < 2; it++)
                    CP_ASYNC16(bBase0 + (uint32_t)s*BSTG + dstPart[it], srcB[it] + s*32);
                CP_COMMIT();
            }
        }

        float acc[2][4][4] = {};

        #pragma unroll 1
        for (int i = 0; i < 8; i++) {
            const int stg = i - (i >= 3 ? 3 : 0) - (i >= 6 ? 3 : 0);   // i % 3
            if (i < 7) { CP_WAIT(1); } else { CP_WAIT(0); }
            __syncthreads();
            if (i + 2 < 8) {
                int s2 = (i+2) - ((i+2) >= 3 ? 3 : 0) - ((i+2) >= 6 ? 3 : 0);
                #pragma unroll
                for (int it = 0; it < 2; it++)
                    CP_ASYNC16(bBase0 + (uint32_t)s2*BSTG + dstPart[it], srcB[it] + (i+2)*32);
                CP_COMMIT();
            }

            const uint32_t aCur = aBase + aLanePart + (uint32_t)i * 64u;
            const uint32_t bCur = bBase0 + (uint32_t)stg * BSTG + bLanePart;

            #pragma unroll
            for (int ks = 0; ks < 32; ks += 16) {
                unsigned afr[2][4];
                #pragma unroll
                for (int ii = 0; ii < 2; ii++) {
                    LDSM4(afr[ii][0], afr[ii][1], afr[ii][2], afr[ii][3],
                          aCur + (uint32_t)ii*(16u*AK_PAD*2u) + (uint32_t)ks*2u);
                }
                unsigned bfr[4][2];
                #pragma unroll
                for (int kh = 0; kh < 2; kh++) {
                    unsigned t0, t1, t2, t3;
                    LDSM4(t0, t1, t2, t3,
                          bCur + (uint32_t)ks*2u + (uint32_t)kh*16u);
                    bfr[0][kh] = t0;
                    bfr[1][kh] = t1;
                    bfr[2][kh] = t2;
                    bfr[3][kh] = t3;
                }
                #pragma unroll
                for (int j = 0; j < 4; j++) {
                    #pragma unroll
                    for (int ii = 0; ii < 2; ii++)
                        asm volatile(
                            "mma.sync.aligned.m16n8k16.row.col.f32.bf16.bf16.f32 "
                            "{%0,%1,%2,%3}, {%4,%5,%6,%7}, {%8,%9}, {%0,%1,%2,%3};"
                            : "+f"(acc[ii][j][0]), "+f"(acc[ii][j][1]),
                              "+f"(acc[ii][j][2]), "+f"(acc[ii][j][3])
                            : "r"(afr[ii][0]), "r"(afr[ii][1]), "r"(afr[ii][2]), "r"(afr[ii][3]),
                              "r"(bfr[j][0]), "r"(bfr[j][1]));
                }
            }
        }

        // epilogue: bias + elu -> bf16 packed stores
        #pragma unroll
        for (int i = 0; i < 2; i++) {
            int r_lo = row0 + mrow0 + i*16 + g;
            #pragma unroll
            for (int j = 0; j < 4; j++) {
                int c = col0 + ncol0 + j*8 + t4*2;
                float bb0 = b2[c], bb1 = b2[c+1];
                *reinterpret_cast<unsigned*>(&h2[(long)r_lo*HH + c]) =
                    packbf2(elu_ff(acc[i][j][0] + bb0), elu_ff(acc[i][j][1] + bb1));
                *reinterpret_cast<unsigned*>(&h2[(long)(r_lo+8)*HH + c]) =
                    packbf2(elu_ff(acc[i][j][2] + bb0), elu_ff(acc[i][j][3] + bb1));
            }
        }
        __syncthreads();
    }
}

// ---------------- vectorized per-node gather sums (bf16 h2, unroll x2) ----------------
__global__ void scatter_kernel(const __nv_bfloat16* __restrict__ h2,
                               const int* __restrict__ list_rec, const int* __restrict__ cnt_rec,
                               const int* __restrict__ list_send, const int* __restrict__ cnt_send,
                               float* __restrict__ inc_raw, float* __restrict__ sq_part,
                               float* __restrict__ out_raw) {
    int id = blockIdx.x;
    bool isOut = id >= ROWS_N;
    int bn = id & (ROWS_N-1);
    int b = bn >> 6, n = bn & 63;
    const int tid = threadIdx.x;
    const int c4 = tid & 63;
    const int rs = tid >> 6;
    const int* __restrict__ list = (isOut ? list_send : list_rec) + n*EE;
    const int cnt = (isOut ? cnt_send : cnt_rec)[n];
    const __nv_bfloat16* __restrict__ hbase = h2 + (long)b*EE*HH + c4*4;

    float4 acc = make_float4(0.f, 0.f, 0.f, 0.f);
    float4 asq = make_float4(0.f, 0.f, 0.f, 0.f);
    int k = rs;
    #pragma unroll 1
    for (; k + 4 < cnt; k += 8) {
        int e0 = list[k];
        int e1 = list[k+4];
        uint2 u0 = *reinterpret_cast<const uint2*>(hbase + (long)e0*HH);
        uint2 u1 = *reinterpret_cast<const uint2*>(hbase + (long)e1*HH);
        {
            __nv_bfloat162 p0 = *reinterpret_cast<__nv_bfloat162*>(&u0.x);
            __nv_bfloat162 p1 = *reinterpret_cast<__nv_bfloat162*>(&u0.y);
            float v0 = __bfloat162float(p0.x), v1 = __bfloat162float(p0.y);
            float v2 = __bfloat162float(p1.x), v3 = __bfloat162float(p1.y);
            acc.x += v0; acc.y += v1; acc.z += v2; acc.w += v3;
            if (!isOut) { asq.x += v0*v0; asq.y += v1*v1; asq.z += v2*v2; asq.w += v3*v3; }
        }
        {
            __nv_bfloat162 p0 = *reinterpret_cast<__nv_bfloat162*>(&u1.x);
            __nv_bfloat162 p1 = *reinterpret_cast<__nv_bfloat162*>(&u1.y);
            float v0 = __bfloat162float(p0.x), v1 = __bfloat162float(p0.y);
            float v2 = __bfloat162float(p1.x), v3 = __bfloat162float(p1.y);
            acc.x += v0; acc.y += v1; acc.z += v2; acc.w += v3;
            if (!isOut) { asq.x += v0*v0; asq.y += v1*v1; asq.z += v2*v2; asq.w += v3*v3; }
        }
    }
    if (k < cnt) {
        int e = list[k];
        uint2 u = *reinterpret_cast<const uint2*>(hbase + (long)e*HH);
        __nv_bfloat162 p0 = *reinterpret_cast<__nv_bfloat162*>(&u.x);
        __nv_bfloat162 p1 = *reinterpret_cast<__nv_bfloat162*>(&u.y);
        float v0 = __bfloat162float(p0.x), v1 = __bfloat162float(p0.y);
        float v2 = __bfloat162float(p1.x), v3 = __bfloat162float(p1.y);
        acc.x += v0; acc.y += v1; acc.z += v2; acc.w += v3;
        if (!isOut) { asq.x += v0*v0; asq.y += v1*v1; asq.z += v2*v2; asq.w += v3*v3; }
    }

    __shared__ float4 sa[4][64];
    __shared__ float4 sq[4][64];
    sa[rs][c4] = acc;
    if (!isOut) sq[rs][c4] = asq;
    __syncthreads();
    if (rs == 0) {
        float4 t = sa[0][c4];
        #pragma unroll
        for (int r = 1; r < 4; r++) {
            float4 u = sa[r][c4];
            t.x += u.x; t.y += u.y; t.z += u.z; t.w += u.w;
        }
        if (!isOut) {
            float4 s = sq[0][c4];
            #pragma unroll
            for (int r = 1; r < 4; r++) {
                float4 u = sq[r][c4];
                s.x += u.x; s.y += u.y; s.z += u.z; s.w += u.w;
            }
            *reinterpret_cast<float4*>(&inc_raw[bn*HH + c4*4]) = t;
            *reinterpret_cast<float4*>(&sq_part[bn*HH + c4*4]) = s;
        } else {
            *reinterpret_cast<float4*>(&out_raw[bn*HH + c4*4]) = t;
        }
    }
}

// ---------------- BN stats -> affine (a,c) ----------------
template<bool SRC_SQ>
__global__ void stats_kernel(const float* __restrict__ sum_part, const float* __restrict__ sq_part,
                             const float* __restrict__ gamma, const float* __restrict__ beta,
                             float* __restrict__ a, float* __restrict__ c,
                             int nrows, float count) {
    int h = blockIdx.x;
    float s = 0.f, sq = 0.f;
    for (int r = threadIdx.x; r < nrows; r += 256) {
        float v = sum_part[r*HH + h];
        s += v;
        if (SRC_SQ) sq += v*v; else sq += sq_part[r*HH + h];
    }
    __shared__ float ss[256], ssq[256];
    ss[threadIdx.x] = s; ssq[threadIdx.x] = sq;
    __syncthreads();
    for (int st = 128; st > 0; st >>= 1) {
        if (threadIdx.x < st) { ss[threadIdx.x] += ss[threadIdx.x+st]; ssq[threadIdx.x] += ssq[threadIdx.x+st]; }
        __syncthreads();
    }
    if (threadIdx.x == 0) {
        float mu = ss[0] / count;
        float var = ssq[0] / count - mu*mu;
        float av = gamma[h] * rsqrtf(var + 1e-5f);
        a[h] = av;
        c[h] = beta[h] - mu * av;
    }
}

// ---------------- launcher ----------------
extern "C" void kernel_launch(void* const* d_in, const int* in_sizes, int n_in,
                              void* d_out, int out_size) {
    const float* centers  = (const float*)d_in[0];
    const float* rel_rec  = (const float*)d_in[1];
    const float* rel_send = (const float*)d_in[2];
    const float* W_traj   = (const float*)d_in[3];
    const float* b_traj   = (const float*)d_in[4];
    const float* n2e_W1   = (const float*)d_in[5];
    const float* n2e_b1   = (const float*)d_in[6];
    const float* n2e_W2   = (const float*)d_in[7];
    const float* n2e_b2   = (const float*)d_in[8];
    const float* n2e_g    = (const float*)d_in[9];
    const float* n2e_be   = (const float*)d_in[10];
    const float* e2n_W1   = (const float*)d_in[11];
    const float* e2n_b1   = (const float*)d_in[12];
    const float* e2n_W2   = (const float*)d_in[13];
    const float* e2n_b2   = (const float*)d_in[14];
    const float* e2n_g    = (const float*)d_in[15];
    const float* e2n_be   = (const float*)d_in[16];
    const float* W_fuse   = (const float*)d_in[17];
    const float* b_fuse   = (const float*)d_in[18];
    const float* W_pred   = (const float*)d_in[19];
    const float* b_pred   = (const float*)d_in[20];
    float* out = (float*)d_out;

    float *p_x, *p_xTop, *p_xBot, *p_inc, *p_incsq, *p_outg;
    float *p_nh1, *p_mraw, *p_fused;
    float *p_ae, *p_ce, *p_an, *p_cn, *p_idr, *p_ids;
    int *p_recv, *p_send, *p_lr, *p_ls, *p_cr, *p_cs;
    __nv_bfloat16 *p_w2t, *p_h2;
    cudaGetSymbolAddress((void**)&p_x, d_x);
    cudaGetSymbolAddress((void**)&p_xTop, d_xTop);
    cudaGetSymbolAddress((void**)&p_xBot, d_xBot);
    cudaGetSymbolAddress((void**)&p_h2, d_h2);
    cudaGetSymbolAddress((void**)&p_inc, d_inc);
    cudaGetSymbolAddress((void**)&p_incsq, d_incsq);
    cudaGetSymbolAddress((void**)&p_outg, d_outg);
    cudaGetSymbolAddress((void**)&p_nh1, d_nh1);
    cudaGetSymbolAddress((void**)&p_mraw, d_mraw);
    cudaGetSymbolAddress((void**)&p_fused, d_fused);
    cudaGetSymbolAddress((void**)&p_ae, d_ae);
    cudaGetSymbolAddress((void**)&p_ce, d_ce);
    cudaGetSymbolAddress((void**)&p_an, d_an);
    cudaGetSymbolAddress((void**)&p_cn, d_cn);
    cudaGetSymbolAddress((void**)&p_idr, d_invdegrec);
    cudaGetSymbolAddress((void**)&p_ids, d_invdegsend);
    cudaGetSymbolAddress((void**)&p_recv, d_recv);
    cudaGetSymbolAddress((void**)&p_send, d_send);
    cudaGetSymbolAddress((void**)&p_lr, d_listrec);
    cudaGetSymbolAddress((void**)&p_ls, d_listsend);
    cudaGetSymbolAddress((void**)&p_cr, d_cntrec);
    cudaGetSymbolAddress((void**)&p_cs, d_cntsend);
    cudaGetSymbolAddress((void**)&p_w2t, d_w2t);

    cudaFuncSetAttribute(edge_gemm2_bf16, cudaFuncAttributeMaxDynamicSharedMemorySize, EDGE_SMEM);
    cudaFuncSetAttribute(mma_gemm_v3<0,false>, cudaFuncAttributeMaxDynamicSharedMemorySize, GEMM_SMEM);
    cudaFuncSetAttribute(mma_gemm_v3<1,true>,  cudaFuncAttributeMaxDynamicSharedMemorySize, GEMM_SMEM);
    cudaFuncSetAttribute(mma_gemm_v3<0,true>,  cudaFuncAttributeMaxDynamicSharedMemorySize, GEMM_SMEM);
    cudaFuncSetAttribute(mma_gemm_v3<2,false>, cudaFuncAttributeMaxDynamicSharedMemorySize, GEMM_SMEM);

    // 1. fused prep: derive + traj + W2^T + per-node lists
    prep_kernel<<<16 + ROWS_N + HH + 128, HH>>>(rel_rec, rel_send, p_recv, p_send,
                                                centers, W_traj, b_traj, n2e_W2, p_w2t, p_x,
                                                p_lr, p_ls, p_cr, p_cs, p_idr, p_ids);

    // 2. xTop/xBot (dual-output, K-step 64)
    mma_gemm_v3<0,false><<<dim3(HH/64, ROWS_N/64, 2), 256, GEMM_SMEM>>>(
        p_x, nullptr, nullptr, nullptr, nullptr, nullptr,
        n2e_W1, n2e_W1 + HH*HH, nullptr, p_xTop, p_xBot, ROWS_N, HH, HH);

    // 3. fused edge MLP v7b (hoisted B prologue)
    edge_gemm2_bf16<<<ROWS_E/A_ROWS, 256, EDGE_SMEM>>>(p_xTop, p_xBot, n2e_b1,
                                                       p_w2t, n2e_b2,
                                                       p_recv, p_send, p_h2);

    // 4. scatter sums (unrolled) + edge BN stats
    scatter_kernel<<<2*ROWS_N, 256>>>(p_h2, p_lr, p_cr, p_ls, p_cs, p_inc, p_incsq, p_outg);
    stats_kernel<false><<<HH, 256>>>(p_inc, p_incsq, n2e_g, n2e_be, p_ae, p_ce, ROWS_N, (float)ROWS_E);

    // 5. node MLP (K-step 64)
    mma_gemm_v3<1,true><<<dim3(HH/64, ROWS_N/64, 1), 256, GEMM_SMEM>>>(
        p_inc, p_outg, p_ae, p_ce, p_idr, p_ids,
        e2n_W1, e2n_W1, e2n_b1, p_nh1, p_nh1, ROWS_N, HH, 2*HH);
    mma_gemm_v3<0,true><<<dim3(HH/64, ROWS_N/64, 1), 256, GEMM_SMEM>>>(
        p_nh1, nullptr, nullptr, nullptr, nullptr, nullptr,
        e2n_W2, e2n_W2, e2n_b2, p_mraw, p_mraw, ROWS_N, HH, HH);
    stats_kernel<true><<<HH, 256>>>(p_mraw, nullptr, e2n_g, e2n_be, p_an, p_cn, ROWS_N, (float)ROWS_N);

    // 6. fuse + predict (+ fused cumsum epilogue)
    mma_gemm_v3<2,false><<<dim3(HH/64, ROWS_N/64, 1), 256, GEMM_SMEM>>>(
        p_x, p_mraw, p_an, p_cn, nullptr, nullptr,
        W_fuse, W_fuse, b_fuse, p_fused, p_fused, ROWS_N, HH, 2*HH);
    pred_pos_kernel<<<dim3(1, ROWS_N/64), 256>>>(p_fused, W_pred, b_pred, centers, out);
}